// round 15
// baseline (speedup 1.0000x reference)
#include <cuda_runtime.h>
#include <cuda_fp16.h>
#include <math.h>
#include <stdint.h>

#define NTOK 1024
#define DINV 512
#define NFV  4
#define NHV  8
#define HDV  64

#define LOG2E 1.44269504f

// -------- scratch (device globals; no allocation allowed) --------
__device__ float  g_cm[2][NFV][DINV];
__device__ __half g_xh[NFV * NTOK * DINV];
__device__ __half g_wq_h[3 * DINV * DINV];
__device__ __half g_wp_h[DINV * DINV];
__device__ __half g_qh[NHV * NFV * NTOK * HDV];      // scaled hd^-0.5 * log2e
__device__ __half g_kh[NHV * NFV * NTOK * HDV];
__device__ __half g_vT[NHV * NFV * HDV * NTOK];      // [hf][d][n]
__device__ __half g_yh[NFV * NTOK * DINV];           // yhat * cm1
__device__ __half g_callTh[NTOK * 8];                // [c][f-pad8]

// ============================================================
// helpers
// ============================================================
__device__ __forceinline__ uint32_t ex2h2(uint32_t x) {
    uint32_t r;
    asm("ex2.approx.f16x2 %0, %1;" : "=r"(r) : "r"(x));
    return r;
}
__device__ __forceinline__ uint32_t packh2(float a, float b) {
    __half2 h = __floats2half2_rn(a, b);
    return *(uint32_t*)&h;
}
__device__ __forceinline__ uint32_t hmul2u(uint32_t a, uint32_t b) {
    uint32_t r;
    asm("mul.f16x2 %0, %1, %2;" : "=r"(r) : "r"(a), "r"(b));
    return r;
}
__device__ __forceinline__ float2 h2f2(uint32_t x) {
    __half2 h = *(__half2*)&x;
    return __half22float2(h);
}

__device__ __forceinline__ void mma_f16(float* d, uint32_t a0, uint32_t a1,
                                        uint32_t a2, uint32_t a3,
                                        uint32_t b0, uint32_t b1) {
    asm volatile(
        "mma.sync.aligned.m16n8k16.row.col.f32.f16.f16.f32 "
        "{%0,%1,%2,%3}, {%4,%5,%6,%7}, {%8,%9}, {%0,%1,%2,%3};"
        : "+f"(d[0]), "+f"(d[1]), "+f"(d[2]), "+f"(d[3])
        : "r"(a0), "r"(a1), "r"(a2), "r"(a3), "r"(b0), "r"(b1));
}

__device__ __forceinline__ void mma_f16_k8(float* d, uint32_t a0, uint32_t a1, uint32_t b0) {
    asm volatile(
        "mma.sync.aligned.m16n8k8.row.col.f32.f16.f16.f32 "
        "{%0,%1,%2,%3}, {%4,%5}, {%6}, {%0,%1,%2,%3};"
        : "+f"(d[0]), "+f"(d[1]), "+f"(d[2]), "+f"(d[3])
        : "r"(a0), "r"(a1), "r"(b0));
}

__device__ __forceinline__ void ldsm_x4(uint32_t& r0, uint32_t& r1,
                                        uint32_t& r2, uint32_t& r3, uint32_t addr) {
    asm volatile("ldmatrix.sync.aligned.m8n8.x4.shared.b16 {%0,%1,%2,%3}, [%4];"
                 : "=r"(r0), "=r"(r1), "=r"(r2), "=r"(r3) : "r"(addr));
}

__device__ __forceinline__ uint32_t smem_u32(const void* p) {
    uint32_t a;
    asm("{ .reg .u64 t; cvta.to.shared.u64 t, %1; cvt.u32.u64 %0, t; }" : "=r"(a) : "l"(p));
    return a;
}

__device__ __forceinline__ void cp_async16(uint32_t dst, const void* src) {
    asm volatile("cp.async.cg.shared.global [%0], [%1], 16;" :: "r"(dst), "l"(src) : "memory");
}
#define CP_COMMIT() asm volatile("cp.async.commit_group;" ::: "memory")
#define CP_WAIT0()  asm volatile("cp.async.wait_group 0;" ::: "memory")
#define CP_WAIT1()  asm volatile("cp.async.wait_group 1;" ::: "memory")

// attn: stage K tile (128 x 64 halves, stride 72 halves)
__device__ __forceinline__ void stage_k(uint32_t dstbase, const __half* src, int tid) {
    #pragma unroll
    for (int i = tid; i < 1024; i += 256) {
        int r = i >> 3, c8 = (i & 7) << 3;
        cp_async16(dstbase + (uint32_t)(r * 144 + c8 * 2), src + r * 64 + c8);
    }
}
// attn: stage V tile (64 x 128 halves transposed, stride 136 halves)
__device__ __forceinline__ void stage_v(uint32_t dstbase, const __half* srcT, int tid) {
    #pragma unroll
    for (int i = tid; i < 1024; i += 256) {
        int r = i >> 4, c16 = (i & 15) << 3;
        cp_async16(dstbase + (uint32_t)(r * 272 + c16 * 2), srcT + (size_t)r * NTOK + c16);
    }
}
// gemm: stage ROWS x 64 half tile from 512-stride, smem stride 72 halves
template <int ROWS>
__device__ __forceinline__ void stage_hr(uint32_t dstbase, const __half* src, int tid) {
    #pragma unroll
    for (int i = tid; i < ROWS * 8; i += 256) {
        int r = i >> 3, c8 = (i & 7) << 3;
        cp_async16(dstbase + (uint32_t)(r * 144 + c8 * 2), src + (size_t)r * 512 + c8);
    }
}

// ============================================================
// merged prep0: block 0 = code_mod LayerNorm; blocks 1-2 = callTh;
// blocks 3-514 = weight fp16 convert. 512 threads.
// ============================================================
__global__ __launch_bounds__(512) void prep0(
    const float* __restrict__ wc, const float* __restrict__ code,
    const float* __restrict__ gq, const float* __restrict__ bq,
    const float* __restrict__ gp, const float* __restrict__ bp,
    const float* __restrict__ cin,
    const float* __restrict__ Wq, const float* __restrict__ Wp)
{
    const int b = blockIdx.x, tid = threadIdx.x;
    if (b == 0) {
        __shared__ float codes[512];
        __shared__ float tsh[NFV][512];
        __shared__ float red[512];
        const int warp = tid >> 5, lane = tid & 31;
        codes[tid] = code[tid];
        __syncthreads();
        const float* cp = &codes[lane * 16];
        for (int i = 0; i < 32; i++) {
            int d = warp * 32 + i;
            float4 w = *(const float4*)(wc + (size_t)d * 128 + lane * 4);
            float t0 = w.x * cp[0] + w.y * cp[4] + w.z * cp[8]  + w.w * cp[12];
            float t1 = w.x * cp[1] + w.y * cp[5] + w.z * cp[9]  + w.w * cp[13];
            float t2 = w.x * cp[2] + w.y * cp[6] + w.z * cp[10] + w.w * cp[14];
            float t3 = w.x * cp[3] + w.y * cp[7] + w.z * cp[11] + w.w * cp[15];
            #pragma unroll
            for (int o = 16; o; o >>= 1) {
                t0 += __shfl_xor_sync(0xffffffffu, t0, o);
                t1 += __shfl_xor_sync(0xffffffffu, t1, o);
                t2 += __shfl_xor_sync(0xffffffffu, t2, o);
                t3 += __shfl_xor_sync(0xffffffffu, t3, o);
            }
            if (lane == 0) {
                tsh[0][d] = t0; tsh[1][d] = t1; tsh[2][d] = t2; tsh[3][d] = t3;
            }
        }
        __syncthreads();
        float gqd = gq[tid], bqd = bq[tid], gpd = gp[tid], bpd = bp[tid];
        for (int f = 0; f < NFV; f++) {
            float t = tsh[f][tid];
            red[tid] = t;
            __syncthreads();
            for (int s = 256; s > 0; s >>= 1) {
                if (tid < s) red[tid] += red[tid + s];
                __syncthreads();
            }
            float mu = red[0] * (1.f / 512.f);
            __syncthreads();
            float dv = t - mu;
            red[tid] = dv * dv;
            __syncthreads();
            for (int s = 256; s > 0; s >>= 1) {
                if (tid < s) red[tid] += red[tid + s];
                __syncthreads();
            }
            float var = red[0] * (1.f / 512.f);
            __syncthreads();
            float nrm = dv * rsqrtf(var + 1e-5f);
            g_cm[0][f][tid] = nrm * gqd + bqd;
            g_cm[1][f][tid] = nrm * gpd + bpd;
        }
    } else if (b <= 2) {
        int c = (b - 1) * 512 + tid;
        __half2 w01 = __floats2half2_rn(cin[c], cin[NTOK + c]);
        __half2 w23 = __floats2half2_rn(cin[2 * NTOK + c], cin[3 * NTOK + c]);
        uint4 v;
        v.x = *(uint32_t*)&w01;
        v.y = *(uint32_t*)&w23;
        v.z = 0u; v.w = 0u;
        *(uint4*)&g_callTh[c * 8] = v;
    } else {
        int i = (b - 3) * 512 + tid;        // float4 index, 262144 total
        if (i < 196608) {
            float4 v = *(const float4*)(Wq + (size_t)i * 4);
            __half* d = g_wq_h + (size_t)i * 4;
            *(__half2*)(d)     = __floats2half2_rn(v.x, v.y);
            *(__half2*)(d + 2) = __floats2half2_rn(v.z, v.w);
        } else {
            int j = i - 196608;
            float4 v = *(const float4*)(Wp + (size_t)j * 4);
            __half* d = g_wp_h + (size_t)j * 4;
            *(__half2*)(d)     = __floats2half2_rn(v.x, v.y);
            *(__half2*)(d + 2) = __floats2half2_rn(v.z, v.w);
        }
    }
}

// xh = half(x * cm0); grid (512, 4), 256 threads
__global__ __launch_bounds__(256) void prep_xh(const float* __restrict__ x) {
    int f = blockIdx.y;
    int i = blockIdx.x * 256 + threadIdx.x;
    int n = i >> 7, c4 = (i & 127) << 2;
    float4 v = *(const float4*)(x + (size_t)n * 512 + c4);
    float4 s = *(const float4*)(&g_cm[0][f][c4]);
    __half* dst = g_xh + (size_t)f * NTOK * DINV + (size_t)n * 512 + c4;
    *(__half2*)(dst)     = __floats2half2_rn(v.x * s.x, v.y * s.y);
    *(__half2*)(dst + 2) = __floats2half2_rn(v.z * s.z, v.w * s.w);
}

// ============================================================
// fp16 GEMM: MT m-tiles of 16 per wm (block M = MT*32)
// MODE 0: xh @ Wq -> q/k/vT ; MODE 1: yh @ Wp -> out
// ============================================================
template <int MODE, int MT>
__global__ __launch_bounds__(256, 2) void gemm_h(
    const float* __restrict__ bias, float* __restrict__ Out)
{
    constexpr int ASZ = MT * 32 * 72;               // halves
    extern __shared__ __half smh[];
    float* sbias = (float*)(smh + 2 * ASZ + 18432);
    const int f   = blockIdx.z;
    const int bm0 = blockIdx.y * (MT * 32);
    const int bn0 = blockIdx.x * 128;
    const int tid = threadIdx.x;
    const int warp = tid >> 5, lane = tid & 31;
    const int gid = lane >> 2, tig = lane & 3;
    const int wm = warp >> 2, wn = warp & 3;

    const int rA = (lane & 7) + (((lane >> 3) & 1) << 3);
    const int kA = (lane >> 4) << 3;
    const uint32_t aofs = (uint32_t)(rA * 144 + kA * 2);
    const int rB = (lane & 7) + ((lane >> 4) << 3);
    const int kB = ((lane >> 3) & 1) << 3;
    const uint32_t bofs = (uint32_t)(rB * 144 + kB * 2);

    const __half* A  = (MODE == 0 ? g_xh : g_yh) + (size_t)f * NTOK * DINV + (size_t)bm0 * 512;
    const __half* Bw = (MODE == 0 ? g_wq_h : g_wp_h) + (size_t)bn0 * 512;

    uint32_t sb = smem_u32(smh);
    uint32_t Ab[2] = {sb, sb + ASZ * 2};
    uint32_t Bb[2] = {sb + 4 * ASZ, sb + 4 * ASZ + 9216 * 2};

    if (tid < 128) sbias[tid] = bias[bn0 + tid];

    stage_hr<MT * 32>(Ab[0], A, tid);
    stage_hr<128>(Bb[0], Bw, tid);
    CP_COMMIT();

    float d[MT][4][4];
    #pragma unroll
    for (int mt = 0; mt < MT; mt++)
        #pragma unroll
        for (int nt = 0; nt < 4; nt++)
            #pragma unroll
            for (int q = 0; q < 4; q++) d[mt][nt][q] = 0.f;

    for (int c = 0; c < 8; c++) {
        if (c < 7) {
            stage_hr<MT * 32>(Ab[(c + 1) & 1], A + (c + 1) * 64, tid);
            stage_hr<128>(Bb[(c + 1) & 1], Bw + (c + 1) * 64, tid);
            CP_COMMIT();
            CP_WAIT1();
        } else {
            CP_WAIT0();
        }
        __syncthreads();
        uint32_t atile = Ab[c & 1];
        uint32_t btile = Bb[c & 1];
        #pragma unroll
        for (int kk = 0; kk < 4; kk++) {
            uint32_t aa[MT][4], bb[4][2];
            #pragma unroll
            for (int mt = 0; mt < MT; mt++)
                ldsm_x4(aa[mt][0], aa[mt][1], aa[mt][2], aa[mt][3],
                        atile + (uint32_t)((wm * (MT * 16) + mt * 16) * 144 + kk * 32) + aofs);
            #pragma unroll
            for (int ntp = 0; ntp < 2; ntp++)
                ldsm_x4(bb[ntp * 2][0], bb[ntp * 2][1], bb[ntp * 2 + 1][0], bb[ntp * 2 + 1][1],
                        btile + (uint32_t)((wn * 32 + ntp * 16) * 144 + kk * 32) + bofs);
            #pragma unroll
            for (int mt = 0; mt < MT; mt++)
                #pragma unroll
                for (int nt = 0; nt < 4; nt++)
                    mma_f16(d[mt][nt], aa[mt][0], aa[mt][1], aa[mt][2], aa[mt][3],
                            bb[nt][0], bb[nt][1]);
        }
        __syncthreads();
    }

    if (MODE == 1) {
        float* outp = Out + (size_t)f * NTOK * DINV;
        #pragma unroll
        for (int mt = 0; mt < MT; mt++) {
            int m0 = bm0 + wm * (MT * 16) + mt * 16 + gid;
            #pragma unroll
            for (int nt = 0; nt < 4; nt++) {
                int jl = wn * 32 + nt * 8 + tig * 2;
                float b0 = sbias[jl], b1 = sbias[jl + 1];
                float2 v0 = {d[mt][nt][0] + b0, d[mt][nt][1] + b1};
                float2 v1 = {d[mt][nt][2] + b0, d[mt][nt][3] + b1};
                *(float2*)(outp + (size_t)m0 * 512 + bn0 + jl)       = v0;
                *(float2*)(outp + (size_t)(m0 + 8) * 512 + bn0 + jl) = v1;
            }
        }
    } else if (bn0 < 1024) {
        int jb = bn0 + wn * 32;
        int tt = jb >> 9;
        int h  = (jb >> 6) & 7;
        int db = jb & 63;
        float mul = (tt == 0) ? (0.125f * LOG2E) : 1.0f;
        __half* base = (tt == 0 ? g_qh : g_kh) + (size_t)((h * NFV + f) * NTOK) * HDV;
        #pragma unroll
        for (int mt = 0; mt < MT; mt++) {
            int m0 = bm0 + wm * (MT * 16) + mt * 16 + gid;
            #pragma unroll
            for (int nt = 0; nt < 4; nt++) {
                int jl = wn * 32 + nt * 8 + tig * 2;
                int dc = db + nt * 8 + tig * 2;
                float b0 = sbias[jl], b1 = sbias[jl + 1];
                __half2 h0 = __floats2half2_rn((d[mt][nt][0] + b0) * mul,
                                               (d[mt][nt][1] + b1) * mul);
                __half2 h1 = __floats2half2_rn((d[mt][nt][2] + b0) * mul,
                                               (d[mt][nt][3] + b1) * mul);
                *(__half2*)(base + (size_t)m0 * HDV + dc)       = h0;
                *(__half2*)(base + (size_t)(m0 + 8) * HDV + dc) = h1;
            }
        }
    } else {
        __syncthreads();
        __half* T = smh;               // 128 x 136 halves (fits in A region for MT=4)
        #pragma unroll
        for (int mt = 0; mt < MT; mt++) {
            int mloc = wm * (MT * 16) + mt * 16 + gid;
            #pragma unroll
            for (int nt = 0; nt < 4; nt++) {
                int jl = wn * 32 + nt * 8 + tig * 2;
                float b0 = sbias[jl], b1 = sbias[jl + 1];
                T[jl * 136 + mloc]           = __float2half_rn(d[mt][nt][0] + b0);
                T[(jl + 1) * 136 + mloc]     = __float2half_rn(d[mt][nt][1] + b1);
                T[jl * 136 + mloc + 8]       = __float2half_rn(d[mt][nt][2] + b0);
                T[(jl + 1) * 136 + mloc + 8] = __float2half_rn(d[mt][nt][3] + b1);
            }
        }
        __syncthreads();
        int vbase = bn0 - 1024;
        #pragma unroll
        for (int t = 0; t < MT * 2; t++) {
            int i = tid + t * 256;
            int jl = i >> (MT == 4 ? 4 : 3);
            int c8 = (MT == 4 ? (i & 15) : (i & 7)) << 3;
            uint4 v = *(uint4*)&T[jl * 136 + c8];
            int vcol = vbase + jl;
            __half* dst = g_vT + (size_t)(((vcol >> 6) * NFV + f) * HDV + (vcol & 63)) * NTOK
                          + bm0 + c8;
            *(uint4*)dst = v;
        }
    }
}

// ============================================================
// attention: flash-style, 128-row blocks, 256 threads, 2 blocks/SM.
// Pass 1 uses 4-buffer K ring (1 sync/iter); pass 2 double-buffered KV pairs.
// smem: B0..B3 @ 0/18432/36864/55296 | Q @ 73728 | WT @ 92160 | tot 108544
// ============================================================
#define AT_B0   0
#define AT_B1   18432
#define AT_B2   36864
#define AT_B3   55296
#define AT_Q    73728
#define AT_WT   92160
#define ATTN_SMEM_BYTES 108544

__global__ __launch_bounds__(256, 2) void attn_kernel(const float* __restrict__ cin)
{
    extern __shared__ char smc[];
    __half* Qs = (__half*)(smc + AT_Q);

    const int tid = threadIdx.x;
    const int warp = tid >> 5, lane = tid & 31;
    const int gid = lane >> 2, tig = lane & 3;
    const int n0 = blockIdx.x * 128;
    const int hf = blockIdx.y;
    const int h = hf >> 2, f = hf & 3;
    const size_t hb = (size_t)hf * NTOK * HDV;

    const int rB = (lane & 7) + ((lane >> 4) << 3);
    const int kB = ((lane >> 3) & 1) << 3;
    const uint32_t bofsK = (uint32_t)(rB * 144 + kB * 2);
    const uint32_t bofsV = (uint32_t)(rB * 272 + kB * 2);

    uint32_t sb = smem_u32(smc);
    uint32_t buf[4] = {sb + AT_B0, sb + AT_B1, sb + AT_B2, sb + AT_B3};
    uint32_t wt = sb + AT_WT;
    const __half* Kp  = g_kh + hb;
    const __half* VTp = g_vT + (size_t)hf * HDV * NTOK;

    // pass-1 prologue: K0 + WT; K1
    stage_k(buf[0], Kp, tid);
    #pragma unroll
    for (int i = tid; i < 1024; i += 256)
        cp_async16(wt + (uint32_t)i * 16, g_callTh + i * 8);
    CP_COMMIT();
    stage_k(buf[1], Kp + 8192, tid);  CP_COMMIT();

    // Q: 128 rows x 64 halves -> stride 72
    #pragma unroll
    for (int i = tid; i < 1024; i += 256) {
        int r = i >> 3, c8 = (i & 7) << 3;
        uint4 v = *(const uint4*)(g_qh + hb + (size_t)(n0 + r) * HDV + c8);
        *(uint4*)((char*)Qs + r * 144 + c8 * 2) = v;
    }
    __syncthreads();

    const int r0 = warp * 16 + gid, r1 = r0 + 8;

    uint32_t aq0[4], aq1[4], aq2[4], aq3[4];
    {
        const __half* q0 = Qs + r0 * 72;
        const __half* q1 = Qs + r1 * 72;
        #pragma unroll
        for (int kk = 0; kk < 4; kk++) {
            aq0[kk] = *(const uint32_t*)&q0[kk * 16 + tig * 2];
            aq1[kk] = *(const uint32_t*)&q1[kk * 16 + tig * 2];
            aq2[kk] = *(const uint32_t*)&q0[kk * 16 + tig * 2 + 8];
            aq3[kk] = *(const uint32_t*)&q1[kk * 16 + tig * 2 + 8];
        }
    }

    // ---- pass 1: s1 = sum 2^s, 4-buffer ring, 1 sync/iter ----
    float l0 = 0.f, l1 = 0.f;
    for (int mt = 0; mt < 8; mt++) {
        if (mt < 6) { CP_WAIT1(); } else { CP_WAIT0(); }
        __syncthreads();
        if (mt < 6) {
            stage_k(buf[(mt + 2) & 3], Kp + (size_t)(mt + 2) * 8192, tid);
            CP_COMMIT();
        }
        uint32_t kb_base = buf[mt & 3];
        #pragma unroll
        for (int ntp = 0; ntp < 8; ntp++) {
            float s4a[4] = {0.f, 0.f, 0.f, 0.f};
            float s4b[4] = {0.f, 0.f, 0.f, 0.f};
            #pragma unroll
            for (int kk = 0; kk < 4; kk++) {
                uint32_t b0, b1, b2, b3;
                ldsm_x4(b0, b1, b2, b3,
                        kb_base + (uint32_t)(ntp * 16 * 144 + kk * 32) + bofsK);
                mma_f16(s4a, aq0[kk], aq1[kk], aq2[kk], aq3[kk], b0, b1);
                mma_f16(s4b, aq0[kk], aq1[kk], aq2[kk], aq3[kk], b2, b3);
            }
            float2 eA0 = h2f2(ex2h2(packh2(s4a[0], s4a[1])));
            float2 eA1 = h2f2(ex2h2(packh2(s4a[2], s4a[3])));
            float2 eB0 = h2f2(ex2h2(packh2(s4b[0], s4b[1])));
            float2 eB1 = h2f2(ex2h2(packh2(s4b[2], s4b[3])));
            l0 += (eA0.x + eA0.y) + (eB0.x + eB0.y);
            l1 += (eA1.x + eA1.y) + (eB1.x + eB1.y);
        }
    }
    l0 += __shfl_xor_sync(0xffffffffu, l0, 1);
    l0 += __shfl_xor_sync(0xffffffffu, l0, 2);
    l1 += __shfl_xor_sync(0xffffffffu, l1, 1);
    l1 += __shfl_xor_sync(0xffffffffu, l1, 2);
    const float i1r0 = 1.f / l0, i1r1 = 1.f / l1;

    // transition: all warps done reading ring before restaging
    __syncthreads();
    stage_k(buf[0], Kp, tid);        stage_v(buf[1], VTp, tid);       CP_COMMIT();
    stage_k(buf[2], Kp + 8192, tid); stage_v(buf[3], VTp + 128, tid); CP_COMMIT();

    // compat A-fragment: rows scaled by inv1*log2e
    uint32_t ca0u, ca1u;
    {
        __half2 a0, a1;
        if (tig < 2) {
            float c00 = cin[(tig * 2) * NTOK + n0 + r0];
            float c01 = cin[(tig * 2 + 1) * NTOK + n0 + r0];
            float c10 = cin[(tig * 2) * NTOK + n0 + r1];
            float c11 = cin[(tig * 2 + 1) * NTOK + n0 + r1];
            a0 = __floats2half2_rn(c00 * i1r0 * LOG2E, c01 * i1r0 * LOG2E);
            a1 = __floats2half2_rn(c10 * i1r1 * LOG2E, c11 * i1r1 * LOG2E);
        } else {
            a0 = __floats2half2_rn(0.f, 0.f);
            a1 = a0;
        }
        ca0u = *(uint32_t*)&a0;
        ca1u = *(uint32_t*)&a1;
    }

    // ---- pass 2 ----
    float o[8][4];
    #pragma unroll
    for (int dt = 0; dt < 8; dt++)
        #pragma unroll
        for (int q = 0; q < 4; q++) o[dt][q] = 0.f;
    float s2l0 = 0.f, s2l1 = 0.f;

    for (int mt = 0; mt < 8; mt++) {
        if (mt < 6) { CP_WAIT1(); } else { CP_WAIT0(); }
        __syncthreads();
        uint32_t kb_base = buf[(mt & 1) * 2];
        uint32_t vb_base = buf[(mt & 1) * 2 + 1];

        #pragma unroll
        for (int half = 0; half < 2; half++) {
            uint32_t bw[8];
            {
                int cbase = mt * 128 + half * 64;
                ldsm_x4(bw[0], bw[1], bw[2], bw[3], wt + (uint32_t)(cbase + lane) * 16);
                ldsm_x4(bw[4], bw[5], bw[6], bw[7], wt + (uint32_t)(cbase + 32 + lane) * 16);
            }
            uint32_t ph0[8], ph1[8];
            #pragma unroll
            for (int ntp = 0; ntp < 4; ntp++) {
                float s4a[4] = {0.f, 0.f, 0.f, 0.f};
                float s4b[4] = {0.f, 0.f, 0.f, 0.f};
                #pragma unroll
                for (int kk = 0; kk < 4; kk++) {
                    uint32_t b0, b1, b2, b3;
                    ldsm_x4(b0, b1, b2, b3,
                            kb_base + (uint32_t)((half * 64 + ntp * 16) * 144 + kk * 32) + bofsK);
                    mma_f16(s4a, aq0[kk], aq1[kk], aq2[kk], aq3[kk], b0, b1);
                    mma_f16(s4b, aq0[kk], aq1[kk], aq2[kk], aq3[kk], b2, b3);
                }
                float cc0[4] = {0.f, 0.f, 0.f, 0.f};
                float cc1[4] = {0.f, 0.f, 0.f, 0.f};
                mma_f16_k8(cc0, ca0u, ca1u, bw[ntp * 2]);
                mma_f16_k8(cc1, ca0u, ca1u, bw[ntp * 2 + 1]);

                uint32_t pA = ex2h2(hmul2u(ex2h2(packh2(s4a[0], s4a[1])),
                                           packh2(cc0[0], cc0[1])));
                uint32_t pB = ex2h2(hmul2u(ex2h2(packh2(s4a[2], s4a[3])),
                                           packh2(cc0[2], cc0[3])));
                uint32_t pC = ex2h2(hmul2u(ex2h2(packh2(s4b[0], s4b[1])),
                                           packh2(cc1[0], cc1[1])));
                uint32_t pD = ex2h2(hmul2u(ex2h2(packh2(s4b[2], s4b[3])),
                                           packh2(cc1[2], cc1[3])));
                float2 fA = h2f2(pA), fB = h2f2(pB), fC = h2f2(pC), fD = h2f2(pD);
                s2l0 += (fA.x + fA.y) + (fC.x + fC.y);
                s2l1 += (fB.x + fB.y) + (fD.x + fD.y);
                ph0[ntp * 2]     = pA;
                ph1[ntp * 2]     = pB;
                ph0[ntp * 2 + 1] = pC;
                ph1[ntp * 2 + 1] = pD;
            }
            #pragma unroll
            for (int kb = 0; kb < 4; kb++) {
                uint32_t a0 = ph0[2 * kb], a1 = ph1[2 * kb];
                uint32_t a2 = ph0[2 * kb + 1], a3 = ph1[2 * kb + 1];
                #pragma unroll
                for (int dtp = 0; dtp < 4; dtp++) {
                    uint32_t v0, v1, v2, v3;
                    ldsm_x4(v0, v1, v2, v3,
                            vb_base + (uint32_t)(dtp * 16 * 272 + (half * 4 + kb) * 32) + bofsV);
                    mma_f16(o[dtp * 2],     a0, a1, a2, a3, v0, v1);
                    mma_f16(o[dtp * 2 + 1], a0, a1, a2, a3, v2, v3);
                }
            }
        }
        __syncthreads();
        if (mt < 6) {
            stage_k(buf[(mt & 1) * 2], Kp + (size_t)(mt + 2) * 8192, tid);
            stage_v(buf[(mt & 1) * 2 + 1], VTp + (mt + 2) * 128, tid);
            CP_COMMIT();
        }
    }

    s2l0 += __shfl_xor_sync(0xffffffffu, s2l0, 1);
    s2l0 += __shfl_xor_sync(0xffffffffu, s2l0, 2);
    s2l1 += __shfl_xor_sync(0xffffffffu, s2l1, 1);
    s2l1 += __shfl_xor_sync(0xffffffffu, s2l1, 2);
    const float i2r0 = 1.f / s2l0, i2r1 = 1.f / s2l1;

    const float* cm1p = &g_cm[1][f][h * 64];
    __half* yp0 = g_yh + (size_t)f * NTOK * DINV + (size_t)(n0 + r0) * DINV + h * 64;
    __half* yp1 = g_yh + (size_t)f * NTOK * DINV + (size_t)(n0 + r1) * DINV + h * 64;
    #pragma unroll
    for (int dt = 0; dt < 8; dt++) {
        int dc = dt * 8 + tig * 2;
        float2 cc = *(const float2*)&cm1p[dc];
        *(__half2*)(yp0 + dc) = __floats2half2_rn(o[dt][0] * i2r0 * cc.x,
                                                  o[dt][1] * i2r0 * cc.y);
        *(__half2*)(yp1 + dc) = __floats2half2_rn(o[dt][2] * i2r1 * cc.x,
                                                  o[dt][3] * i2r1 * cc.y);
    }
}

// ============================================================
extern "C" void kernel_launch(void* const* d_in, const int* in_sizes, int n_in,
                              void* d_out, int out_size)
{
    const float* x      = (const float*)d_in[0];
    const float* compat = (const float*)d_in[1];
    const float* code   = (const float*)d_in[2];
    const float* wc     = (const float*)d_in[3];
    const float* Wqkv   = (const float*)d_in[4];
    const float* bqkv   = (const float*)d_in[5];
    const float* Wproj  = (const float*)d_in[6];
    const float* bproj  = (const float*)d_in[7];
    const float* lnqg   = (const float*)d_in[8];
    const float* lnqb   = (const float*)d_in[9];
    const float* lnpg   = (const float*)d_in[10];
    const float* lnpb   = (const float*)d_in[11];
    float* out = (float*)d_out;

    constexpr int GH4_BYTES = (2 * 9216 + 18432) * 2 + 512;   // MT=4
    constexpr int GH2_BYTES = (2 * 4608 + 18432) * 2 + 512;   // MT=2

    cudaFuncSetAttribute(attn_kernel,
                         cudaFuncAttributeMaxDynamicSharedMemorySize, ATTN_SMEM_BYTES);
    cudaFuncSetAttribute((gemm_h<0, 4>),
                         cudaFuncAttributeMaxDynamicSharedMemorySize, GH4_BYTES);
    cudaFuncSetAttribute((gemm_h<1, 2>),
                         cudaFuncAttributeMaxDynamicSharedMemorySize, GH2_BYTES);

    prep0<<<515, 512>>>(wc, code, lnqg, lnqb, lnpg, lnpb, compat, Wqkv, Wproj);
    prep_xh<<<dim3(512, 4), 256>>>(x);
    gemm_h<0, 4><<<dim3(12, 8, 4), 256, GH4_BYTES>>>(bqkv, nullptr);
    attn_kernel<<<dim3(8, 32), 256, ATTN_SMEM_BYTES>>>(compat);
    gemm_h<1, 2><<<dim3(4, 16, 4), 256, GH2_BYTES>>>(bproj, out);
}